// round 6
// baseline (speedup 1.0000x reference)
#include <cuda_runtime.h>
#include <stdint.h>

// ============================================================================
// TAGNet: 3x TAGConv(K=2) with dropout(0.5, jax threefry key 42) + PReLU
// N=50000 nodes, E=800000 edges, 64 -> 64 -> 64 -> 1
// edge_index is int32 (JAX x64 disabled downcasts int64 -> int32).
// ============================================================================

#define NN 50000
#define EE 800000
#define FD 64
// JAX >= 0.4.36 defaults to threefry_partitionable=True. Flip to 0 if rel_err
// indicates the legacy counter layout.
#define JAX_PARTITIONABLE 1

// ---------------- device scratch (static: no allocations allowed) ----------
__device__ float g_deg[NN];
__device__ float g_dinv[NN];
__device__ int   g_cnt[NN];
__device__ int   g_rowptr[NN + 1];
__device__ int   g_src[EE];      // source node per (col-sorted) edge
__device__ float g_w[EE];        // norm per (col-sorted) edge
__device__ float g_T1[NN * FD];
__device__ float g_T2[NN * FD];
__device__ float g_G1[NN * FD];
__device__ float g_G2[NN * FD];

// buffer selector resolved in DEVICE code (legal address-of on device globals)
#define BUF_T1 1
#define BUF_T2 2
#define BUF_G1 3
#define BUF_G2 4
__device__ __forceinline__ float* buf_sel(int s) {
    switch (s) {
        case BUF_T1: return g_T1;
        case BUF_T2: return g_T2;
        case BUF_G1: return g_G1;
        default:     return g_G2;
    }
}

// ---------------- Threefry-2x32 (JAX-compatible, 20 rounds) ----------------
__host__ __device__ __forceinline__ unsigned tf_rotl(unsigned x, int d) {
    return (x << d) | (x >> (32 - d));
}

__host__ __device__ __forceinline__ void tf2x32(unsigned k0, unsigned k1,
                                                unsigned x0, unsigned x1,
                                                unsigned& o0, unsigned& o1) {
    const unsigned ks2 = k0 ^ k1 ^ 0x1BD11BDAu;
    unsigned v0 = x0 + k0;
    unsigned v1 = x1 + k1;
#define TF_R4(a, b, c, d)                                   \
    v0 += v1; v1 = tf_rotl(v1, a); v1 ^= v0;                \
    v0 += v1; v1 = tf_rotl(v1, b); v1 ^= v0;                \
    v0 += v1; v1 = tf_rotl(v1, c); v1 ^= v0;                \
    v0 += v1; v1 = tf_rotl(v1, d); v1 ^= v0;
    TF_R4(13, 15, 26, 6);  v0 += k1;  v1 += ks2 + 1u;
    TF_R4(17, 29, 16, 24); v0 += ks2; v1 += k0 + 2u;
    TF_R4(13, 15, 26, 6);  v0 += k0;  v1 += k1 + 3u;
    TF_R4(17, 29, 16, 24); v0 += k1;  v1 += ks2 + 4u;
    TF_R4(13, 15, 26, 6);  v0 += ks2; v1 += k0 + 5u;
#undef TF_R4
    o0 = v0;
    o1 = v1;
}

// ---------------- graph preprocessing ---------------------------------------
__device__ __forceinline__ int clamp_node(int v) {
    return (v < 0) ? 0 : ((v >= NN) ? NN - 1 : v);
}

__global__ void zero_kernel() {
    int i = blockIdx.x * blockDim.x + threadIdx.x;
    if (i < NN) {
        g_deg[i] = 0.0f;
        g_cnt[i] = 0;
    }
}

__global__ void deg_kernel(const int* __restrict__ ei,
                           const float* __restrict__ ea) {
    int e = blockIdx.x * blockDim.x + threadIdx.x;
    if (e >= EE) return;
    int c = clamp_node(ei[EE + e]);  // col = target
    atomicAdd(&g_deg[c], ea[e]);
    atomicAdd(&g_cnt[c], 1);
}

__global__ void dinv_kernel() {
    int n = blockIdx.x * blockDim.x + threadIdx.x;
    if (n >= NN) return;
    float d = g_deg[n];
    g_dinv[n] = (d > 0.0f) ? rsqrtf(fmaxf(d, 1e-12f)) : 0.0f;
}

// single-block exclusive scan of g_cnt -> g_rowptr, and reset g_cnt
__global__ void scan_kernel() {
    __shared__ int s[1024];
    const int CH = (NN + 1023) / 1024;  // 49
    int t = threadIdx.x;
    int base = t * CH;
    int sum = 0;
    for (int j = 0; j < CH; j++) {
        int idx = base + j;
        if (idx < NN) sum += g_cnt[idx];
    }
    s[t] = sum;
    __syncthreads();
    for (int off = 1; off < 1024; off <<= 1) {
        int v = (t >= off) ? s[t - off] : 0;
        __syncthreads();
        s[t] += v;
        __syncthreads();
    }
    int run = s[t] - sum;  // exclusive prefix
    for (int j = 0; j < CH; j++) {
        int idx = base + j;
        if (idx < NN) {
            g_rowptr[idx] = run;
            run += g_cnt[idx];
            g_cnt[idx] = 0;
        }
    }
    if (t == 1023) g_rowptr[NN] = run;  // total = E
}

__global__ void sort_kernel(const int* __restrict__ ei,
                            const float* __restrict__ ea) {
    int e = blockIdx.x * blockDim.x + threadIdx.x;
    if (e >= EE) return;
    int r = clamp_node(ei[e]);
    int c = clamp_node(ei[EE + e]);
    int p = g_rowptr[c] + atomicAdd(&g_cnt[c], 1);
    if (p < 0) p = 0;
    if (p >= EE) p = EE - 1;
    g_src[p] = r;
    g_w[p] = g_dinv[r] * ea[e] * g_dinv[c];
}

// ---------------- SpMM: hout[n,:] = sum_{e: col=n} w_e * hin[src_e,:] ------
// hin: external pointer if in_sel==0, else selected scratch buffer.
__global__ void spmm_kernel(const float* __restrict__ hin_ext, int in_sel,
                            int out_sel) {
    int warp = (blockIdx.x * blockDim.x + threadIdx.x) >> 5;
    int lane = threadIdx.x & 31;
    if (warp >= NN) return;
    const float* __restrict__ hin = (in_sel == 0) ? hin_ext : buf_sel(in_sel);
    float* __restrict__ hout = buf_sel(out_sel);
    int s = g_rowptr[warp];
    int e = g_rowptr[warp + 1];
    float2 acc = make_float2(0.0f, 0.0f);
    for (int j = s; j < e; j++) {
        int src = g_src[j];
        float w = g_w[j];
        float2 v = *(const float2*)&hin[src * FD + lane * 2];
        acc.x += w * v.x;
        acc.y += w * v.y;
    }
    *(float2*)&hout[warp * FD + lane * 2] = acc;
}

// ---------------- fused dense: out = H@W[0] + T1@W[1] + T2@W[2] (64 cols) ---
#define NPB 16  // nodes per block (256 threads: 16 nodes x 16 threads x 4 cols)
__global__ void dense64_kernel(const float* __restrict__ H_ext, int h_sel,
                               const float* __restrict__ W,  // (3,64,64)
                               int out_sel) {
    __shared__ float sW[3 * 64 * 64];
    for (int i = threadIdx.x; i < 3 * 64 * 64; i += 256) sW[i] = W[i];
    __syncthreads();
    int node = blockIdx.x * NPB + (threadIdx.x >> 4);
    int c0 = (threadIdx.x & 15) * 4;
    if (node >= NN) return;
    const float* __restrict__ H = (h_sel == 0) ? H_ext : buf_sel(h_sel);
    float* __restrict__ out = buf_sel(out_sel);
    const float* h  = H    + node * FD;
    const float* t1 = g_T1 + node * FD;
    const float* t2 = g_T2 + node * FD;
    float a0 = 0, a1 = 0, a2 = 0, a3 = 0;
#pragma unroll 4
    for (int i = 0; i < 64; i++) {
        float hv  = __ldg(&h[i]);
        float t1v = t1[i];
        float t2v = t2[i];
        float4 w0 = *(const float4*)&sW[(0 * 64 + i) * 64 + c0];
        float4 w1 = *(const float4*)&sW[(1 * 64 + i) * 64 + c0];
        float4 w2 = *(const float4*)&sW[(2 * 64 + i) * 64 + c0];
        a0 += hv * w0.x + t1v * w1.x + t2v * w2.x;
        a1 += hv * w0.y + t1v * w1.y + t2v * w2.y;
        a2 += hv * w0.z + t1v * w1.z + t2v * w2.z;
        a3 += hv * w0.w + t1v * w1.w + t2v * w2.w;
    }
    float4 r = make_float4(a0, a1, a2, a3);
    *(float4*)&out[node * FD + c0] = r;
}

// ---------------- final projection to OUT=1: H=g_G2, T1=g_T1, T2=g_T2 -------
__global__ void dense1_kernel(const float* __restrict__ W,  // (3,64,1)
                              float* __restrict__ out) {
    int warp = (blockIdx.x * blockDim.x + threadIdx.x) >> 5;
    int lane = threadIdx.x & 31;
    if (warp >= NN) return;
    int i0 = lane * 2;
    float2 h  = *(const float2*)&g_G2[warp * FD + i0];
    float2 t1 = *(const float2*)&g_T1[warp * FD + i0];
    float2 t2 = *(const float2*)&g_T2[warp * FD + i0];
    float s = h.x * __ldg(&W[i0])        + h.y * __ldg(&W[i0 + 1])
            + t1.x * __ldg(&W[64 + i0])  + t1.y * __ldg(&W[64 + i0 + 1])
            + t2.x * __ldg(&W[128 + i0]) + t2.y * __ldg(&W[128 + i0 + 1]);
#pragma unroll
    for (int off = 16; off; off >>= 1) s += __shfl_down_sync(0xFFFFFFFFu, s, off);
    if (lane == 0) out[warp] = s;
}

// ---------------- dropout (threefry) + PReLU --------------------------------
__global__ void act_kernel(int sel,
                           const float* __restrict__ a_ptr,
                           unsigned k0, unsigned k1) {
    int i = blockIdx.x * blockDim.x + threadIdx.x;
    if (i >= NN * FD) return;
    float* __restrict__ g = buf_sel(sel);
    unsigned b1, b2, bits;
#if JAX_PARTITIONABLE
    tf2x32(k0, k1, 0u, (unsigned)i, b1, b2);
    bits = b1 ^ b2;
#else
    const unsigned HALF = (unsigned)(NN * FD) / 2u;
    if ((unsigned)i < HALF) {
        tf2x32(k0, k1, (unsigned)i, (unsigned)i + HALF, b1, b2);
        bits = b1;
    } else {
        tf2x32(k0, k1, (unsigned)i - HALF, (unsigned)i, b1, b2);
        bits = b2;
    }
#endif
    // uniform(bits) < 0.5  <=>  top bit of bits == 0
    float h = g[i];
    h = (bits & 0x80000000u) ? 0.0f : 2.0f * h;
    float a = __ldg(&a_ptr[0]);
    g[i] = (h >= 0.0f) ? h : a * h;
}

// ============================================================================
extern "C" void kernel_launch(void* const* d_in, const int* in_sizes, int n_in,
                              void* d_out, int out_size) {
    const float* x  = (const float*)d_in[0];
    const int*   ei = (const int*)d_in[1];     // int32: JAX x64-disabled
    const float* ea = (const float*)d_in[2];
    const float* W0 = (const float*)d_in[3];
    const float* W1 = (const float*)d_in[4];
    const float* W2 = (const float*)d_in[5];
    const float* a0 = (const float*)d_in[6];
    const float* a1 = (const float*)d_in[7];
    float* out = (float*)d_out;

    // host-side Threefry: derive dropout subkeys from jax.random.key(42)
    // key data = (hi, lo) = (0, 42)
    unsigned dk0_0, dk0_1, dk1_0, dk1_1;
#if JAX_PARTITIONABLE
    tf2x32(0u, 42u, 0u, 0u, dk0_0, dk0_1);
    tf2x32(0u, 42u, 0u, 1u, dk1_0, dk1_1);
#else
    unsigned A0, A1, B0, B1;
    tf2x32(0u, 42u, 0u, 2u, A0, A1);
    tf2x32(0u, 42u, 1u, 3u, B0, B1);
    dk0_0 = A0; dk0_1 = B0;  // keys mix lanes in legacy split
    dk1_0 = A1; dk1_1 = B1;
#endif

    const int TB = 256;
    const int gN  = (NN + TB - 1) / TB;
    const int gE  = (EE + TB - 1) / TB;
    const int gW  = (NN * 32 + TB - 1) / TB;   // warp per node
    const int gF  = (NN * FD + TB - 1) / TB;
    const int gD  = (NN + NPB - 1) / NPB;

    // ---- graph preprocessing (CSR by target) ----
    zero_kernel<<<gN, TB>>>();
    deg_kernel<<<gE, TB>>>(ei, ea);
    dinv_kernel<<<gN, TB>>>();
    scan_kernel<<<1, 1024>>>();
    sort_kernel<<<gE, TB>>>(ei, ea);

    // ---- layer 0: x -> G1 ----
    spmm_kernel<<<gW, TB>>>(x, 0, BUF_T1);
    spmm_kernel<<<gW, TB>>>(nullptr, BUF_T1, BUF_T2);
    dense64_kernel<<<gD, TB>>>(x, 0, W0, BUF_G1);
    act_kernel<<<gF, TB>>>(BUF_G1, a0, dk0_0, dk0_1);

    // ---- layer 1: G1 -> G2 ----
    spmm_kernel<<<gW, TB>>>(nullptr, BUF_G1, BUF_T1);
    spmm_kernel<<<gW, TB>>>(nullptr, BUF_T1, BUF_T2);
    dense64_kernel<<<gD, TB>>>(nullptr, BUF_G1, W1, BUF_G2);
    act_kernel<<<gF, TB>>>(BUF_G2, a1, dk1_0, dk1_1);

    // ---- layer 2: G2 -> out (N x 1) ----
    spmm_kernel<<<gW, TB>>>(nullptr, BUF_G2, BUF_T1);
    spmm_kernel<<<gW, TB>>>(nullptr, BUF_T1, BUF_T2);
    dense1_kernel<<<gW, TB>>>(W2, out);
}

// round 10
// speedup vs baseline: 1.1817x; 1.1817x over previous
#include <cuda_runtime.h>
#include <stdint.h>

// ============================================================================
// TAGNet: 3x TAGConv(K=2) with dropout(0.5, jax threefry key 42) + PReLU
// N=50000 nodes, E=800000 edges, 64 -> 64 -> 64 -> 1
// R7: parallel scan, float4 half-warp SpMM with packed edges, fused act.
// ============================================================================

#define NN 50000
#define EE 800000
#define FD 64
#define JAX_PARTITIONABLE 1

#define SB 1024
#define NSB ((NN + SB - 1) / SB)   // 49

// ---------------- device scratch (static: no allocations allowed) ----------
__device__ float g_deg[NN];
__device__ float g_dinv[NN];
__device__ int   g_cnt[NN];
__device__ int   g_rowptr[NN + 1];
__device__ int   g_bsum[NSB];
__device__ int   g_boff[NSB];
__device__ int2  g_edge[EE];     // (src, w-as-int) per col-sorted edge
__device__ float g_T1[NN * FD];
__device__ float g_T2[NN * FD];
__device__ float g_G1[NN * FD];
__device__ float g_G2[NN * FD];

#define BUF_T1 1
#define BUF_T2 2
#define BUF_G1 3
#define BUF_G2 4
__device__ __forceinline__ float* buf_sel(int s) {
    switch (s) {
        case BUF_T1: return g_T1;
        case BUF_T2: return g_T2;
        case BUF_G1: return g_G1;
        default:     return g_G2;
    }
}

// ---------------- Threefry-2x32 (JAX-compatible, 20 rounds) ----------------
__host__ __device__ __forceinline__ unsigned tf_rotl(unsigned x, int d) {
    return (x << d) | (x >> (32 - d));
}

__host__ __device__ __forceinline__ void tf2x32(unsigned k0, unsigned k1,
                                                unsigned x0, unsigned x1,
                                                unsigned& o0, unsigned& o1) {
    const unsigned ks2 = k0 ^ k1 ^ 0x1BD11BDAu;
    unsigned v0 = x0 + k0;
    unsigned v1 = x1 + k1;
#define TF_R4(a, b, c, d)                                   \
    v0 += v1; v1 = tf_rotl(v1, a); v1 ^= v0;                \
    v0 += v1; v1 = tf_rotl(v1, b); v1 ^= v0;                \
    v0 += v1; v1 = tf_rotl(v1, c); v1 ^= v0;                \
    v0 += v1; v1 = tf_rotl(v1, d); v1 ^= v0;
    TF_R4(13, 15, 26, 6);  v0 += k1;  v1 += ks2 + 1u;
    TF_R4(17, 29, 16, 24); v0 += ks2; v1 += k0 + 2u;
    TF_R4(13, 15, 26, 6);  v0 += k0;  v1 += k1 + 3u;
    TF_R4(17, 29, 16, 24); v0 += k1;  v1 += ks2 + 4u;
    TF_R4(13, 15, 26, 6);  v0 += ks2; v1 += k0 + 5u;
#undef TF_R4
    o0 = v0;
    o1 = v1;
}

// dropout(0.5) + PReLU on a single value at flat index i
__device__ __forceinline__ float act_apply(float h, unsigned i,
                                           unsigned k0, unsigned k1, float a) {
    unsigned b1, b2;
    tf2x32(k0, k1, 0u, i, b1, b2);
    unsigned bits = b1 ^ b2;
    h = (bits & 0x80000000u) ? 0.0f : 2.0f * h;
    return (h >= 0.0f) ? h : a * h;
}

// ---------------- graph preprocessing ---------------------------------------
__device__ __forceinline__ int clamp_node(int v) {
    return (v < 0) ? 0 : ((v >= NN) ? NN - 1 : v);
}

__global__ void zero_kernel() {
    int i = blockIdx.x * blockDim.x + threadIdx.x;
    if (i < NN) {
        g_deg[i] = 0.0f;
        g_cnt[i] = 0;
    }
}

__global__ void deg_kernel(const int* __restrict__ ei,
                           const float* __restrict__ ea) {
    int e = blockIdx.x * blockDim.x + threadIdx.x;
    if (e >= EE) return;
    int c = clamp_node(ei[EE + e]);  // col = target
    atomicAdd(&g_deg[c], ea[e]);
    atomicAdd(&g_cnt[c], 1);
}

__global__ void dinv_kernel() {
    int n = blockIdx.x * blockDim.x + threadIdx.x;
    if (n >= NN) return;
    float d = g_deg[n];
    g_dinv[n] = (d > 0.0f) ? rsqrtf(fmaxf(d, 1e-12f)) : 0.0f;
}

// ---- parallel exclusive scan of g_cnt -> g_rowptr (3 kernels) ----
__global__ void scan1_kernel() {  // grid NSB, block SB: block sums
    __shared__ int sh[SB];
    int i = blockIdx.x * SB + threadIdx.x;
    sh[threadIdx.x] = (i < NN) ? g_cnt[i] : 0;
    __syncthreads();
    for (int off = SB / 2; off; off >>= 1) {
        if (threadIdx.x < off) sh[threadIdx.x] += sh[threadIdx.x + off];
        __syncthreads();
    }
    if (threadIdx.x == 0) g_bsum[blockIdx.x] = sh[0];
}

__global__ void scan2_kernel() {  // 1 block of 64: scan block sums
    __shared__ int sh[64];
    int t = threadIdx.x;
    int v = (t < NSB) ? g_bsum[t] : 0;
    sh[t] = v;
    __syncthreads();
    for (int off = 1; off < 64; off <<= 1) {
        int u = (t >= off) ? sh[t - off] : 0;
        __syncthreads();
        sh[t] += u;
        __syncthreads();
    }
    if (t < NSB) g_boff[t] = sh[t] - v;   // exclusive
    if (t == 63) g_rowptr[NN] = sh[63];   // total (= EE)
}

__global__ void scan3_kernel() {  // grid NSB, block SB: local scan + offset
    __shared__ int sh[SB];
    int i = blockIdx.x * SB + threadIdx.x;
    int v = (i < NN) ? g_cnt[i] : 0;
    sh[threadIdx.x] = v;
    __syncthreads();
    for (int off = 1; off < SB; off <<= 1) {
        int u = (threadIdx.x >= off) ? sh[threadIdx.x - off] : 0;
        __syncthreads();
        sh[threadIdx.x] += u;
        __syncthreads();
    }
    if (i < NN) {
        g_rowptr[i] = g_boff[blockIdx.x] + sh[threadIdx.x] - v;  // exclusive
        g_cnt[i] = 0;
    }
}

__global__ void sort_kernel(const int* __restrict__ ei,
                            const float* __restrict__ ea) {
    int e = blockIdx.x * blockDim.x + threadIdx.x;
    if (e >= EE) return;
    int r = clamp_node(ei[e]);
    int c = clamp_node(ei[EE + e]);
    int p = g_rowptr[c] + atomicAdd(&g_cnt[c], 1);
    if (p < 0) p = 0;
    if (p >= EE) p = EE - 1;
    float w = g_dinv[r] * ea[e] * g_dinv[c];
    g_edge[p] = make_int2(r, __float_as_int(w));
}

// ---------------- SpMM: half-warp (16 lanes) per node, float4 per lane -----
__global__ void spmm_kernel(const float* __restrict__ hin_ext, int in_sel,
                            int out_sel) {
    int hw = (blockIdx.x * blockDim.x + threadIdx.x) >> 4;  // node
    int lane = threadIdx.x & 15;
    if (hw >= NN) return;
    const float* __restrict__ hin = (in_sel == 0) ? hin_ext : buf_sel(in_sel);
    const float4* __restrict__ hin4 = (const float4*)hin;
    float4* __restrict__ hout4 = (float4*)buf_sel(out_sel);
    int s = g_rowptr[hw];
    int e = g_rowptr[hw + 1];
    float4 acc = make_float4(0.f, 0.f, 0.f, 0.f);
    int j = s;
    for (; j + 4 <= e; j += 4) {
        int2 e0 = g_edge[j];
        int2 e1 = g_edge[j + 1];
        int2 e2 = g_edge[j + 2];
        int2 e3 = g_edge[j + 3];
        float4 v0 = __ldg(&hin4[e0.x * 16 + lane]);
        float4 v1 = __ldg(&hin4[e1.x * 16 + lane]);
        float4 v2 = __ldg(&hin4[e2.x * 16 + lane]);
        float4 v3 = __ldg(&hin4[e3.x * 16 + lane]);
        float w0 = __int_as_float(e0.y);
        float w1 = __int_as_float(e1.y);
        float w2 = __int_as_float(e2.y);
        float w3 = __int_as_float(e3.y);
        acc.x += w0 * v0.x; acc.y += w0 * v0.y; acc.z += w0 * v0.z; acc.w += w0 * v0.w;
        acc.x += w1 * v1.x; acc.y += w1 * v1.y; acc.z += w1 * v1.z; acc.w += w1 * v1.w;
        acc.x += w2 * v2.x; acc.y += w2 * v2.y; acc.z += w2 * v2.z; acc.w += w2 * v2.w;
        acc.x += w3 * v3.x; acc.y += w3 * v3.y; acc.z += w3 * v3.z; acc.w += w3 * v3.w;
    }
    for (; j < e; j++) {
        int2 ed = g_edge[j];
        float w = __int_as_float(ed.y);
        float4 v = __ldg(&hin4[ed.x * 16 + lane]);
        acc.x += w * v.x; acc.y += w * v.y; acc.z += w * v.z; acc.w += w * v.w;
    }
    hout4[hw * 16 + lane] = acc;
}

// ---------------- fused dense + optional dropout/PReLU ----------------------
// out = H@W[0] + T1@W[1] + T2@W[2]; if apply_act: dropout(threefry)+PReLU.
#define NPB 16  // nodes per block (256 threads: 16 nodes x 16 threads x 4 cols)
__global__ void dense64_kernel(const float* __restrict__ H_ext, int h_sel,
                               const float* __restrict__ W,  // (3,64,64)
                               int out_sel, int apply_act,
                               const float* __restrict__ a_ptr,
                               unsigned k0, unsigned k1) {
    __shared__ float sW[3 * 64 * 64];
    for (int i = threadIdx.x; i < 3 * 64 * 64; i += 256) sW[i] = W[i];
    __syncthreads();
    int node = blockIdx.x * NPB + (threadIdx.x >> 4);
    int c0 = (threadIdx.x & 15) * 4;
    if (node >= NN) return;
    const float* __restrict__ H = (h_sel == 0) ? H_ext : buf_sel(h_sel);
    float* __restrict__ out = buf_sel(out_sel);
    const float* h  = H    + node * FD;
    const float* t1 = g_T1 + node * FD;
    const float* t2 = g_T2 + node * FD;
    float a0 = 0, a1 = 0, a2 = 0, a3 = 0;
#pragma unroll 4
    for (int i = 0; i < 64; i++) {
        float hv  = __ldg(&h[i]);
        float t1v = t1[i];
        float t2v = t2[i];
        float4 w0 = *(const float4*)&sW[(0 * 64 + i) * 64 + c0];
        float4 w1 = *(const float4*)&sW[(1 * 64 + i) * 64 + c0];
        float4 w2 = *(const float4*)&sW[(2 * 64 + i) * 64 + c0];
        a0 += hv * w0.x + t1v * w1.x + t2v * w2.x;
        a1 += hv * w0.y + t1v * w1.y + t2v * w2.y;
        a2 += hv * w0.z + t1v * w1.z + t2v * w2.z;
        a3 += hv * w0.w + t1v * w1.w + t2v * w2.w;
    }
    if (apply_act) {
        unsigned base = (unsigned)(node * FD + c0);
        float a = __ldg(&a_ptr[0]);
        a0 = act_apply(a0, base + 0u, k0, k1, a);
        a1 = act_apply(a1, base + 1u, k0, k1, a);
        a2 = act_apply(a2, base + 2u, k0, k1, a);
        a3 = act_apply(a3, base + 3u, k0, k1, a);
    }
    *(float4*)&out[node * FD + c0] = make_float4(a0, a1, a2, a3);
}

// ---------------- final projection to OUT=1: H=g_G2, T1=g_T1, T2=g_T2 -------
__global__ void dense1_kernel(const float* __restrict__ W,  // (3,64,1)
                              float* __restrict__ out) {
    int warp = (blockIdx.x * blockDim.x + threadIdx.x) >> 5;
    int lane = threadIdx.x & 31;
    if (warp >= NN) return;
    int i0 = lane * 2;
    float2 h  = *(const float2*)&g_G2[warp * FD + i0];
    float2 t1 = *(const float2*)&g_T1[warp * FD + i0];
    float2 t2 = *(const float2*)&g_T2[warp * FD + i0];
    float s = h.x * __ldg(&W[i0])        + h.y * __ldg(&W[i0 + 1])
            + t1.x * __ldg(&W[64 + i0])  + t1.y * __ldg(&W[64 + i0 + 1])
            + t2.x * __ldg(&W[128 + i0]) + t2.y * __ldg(&W[128 + i0 + 1]);
#pragma unroll
    for (int off = 16; off; off >>= 1) s += __shfl_down_sync(0xFFFFFFFFu, s, off);
    if (lane == 0) out[warp] = s;
}

// ============================================================================
extern "C" void kernel_launch(void* const* d_in, const int* in_sizes, int n_in,
                              void* d_out, int out_size) {
    const float* x  = (const float*)d_in[0];
    const int*   ei = (const int*)d_in[1];     // int32: JAX x64-disabled
    const float* ea = (const float*)d_in[2];
    const float* W0 = (const float*)d_in[3];
    const float* W1 = (const float*)d_in[4];
    const float* W2 = (const float*)d_in[5];
    const float* a0 = (const float*)d_in[6];
    const float* a1 = (const float*)d_in[7];
    float* out = (float*)d_out;

    // host-side Threefry: dropout subkeys from jax.random.key(42) = (0, 42)
    unsigned dk0_0, dk0_1, dk1_0, dk1_1;
    tf2x32(0u, 42u, 0u, 0u, dk0_0, dk0_1);
    tf2x32(0u, 42u, 0u, 1u, dk1_0, dk1_1);

    const int TB = 256;
    const int gN  = (NN + TB - 1) / TB;
    const int gE  = (EE + TB - 1) / TB;
    const int gHW = (NN * 16 + TB - 1) / TB;   // half-warp per node
    const int gW  = (NN * 32 + TB - 1) / TB;   // warp per node
    const int gD  = (NN + NPB - 1) / NPB;

    // ---- graph preprocessing (CSR by target) ----
    zero_kernel<<<gN, TB>>>();
    deg_kernel<<<gE, TB>>>(ei, ea);
    dinv_kernel<<<gN, TB>>>();
    scan1_kernel<<<NSB, SB>>>();
    scan2_kernel<<<1, 64>>>();
    scan3_kernel<<<NSB, SB>>>();
    sort_kernel<<<gE, TB>>>(ei, ea);

    // ---- layer 0: x -> G1 ----
    spmm_kernel<<<gHW, TB>>>(x, 0, BUF_T1);
    spmm_kernel<<<gHW, TB>>>(nullptr, BUF_T1, BUF_T2);
    dense64_kernel<<<gD, TB>>>(x, 0, W0, BUF_G1, 1, a0, dk0_0, dk0_1);

    // ---- layer 1: G1 -> G2 ----
    spmm_kernel<<<gHW, TB>>>(nullptr, BUF_G1, BUF_T1);
    spmm_kernel<<<gHW, TB>>>(nullptr, BUF_T1, BUF_T2);
    dense64_kernel<<<gD, TB>>>(nullptr, BUF_G1, W1, BUF_G2, 1, a1, dk1_0, dk1_1);

    // ---- layer 2: G2 -> out (N x 1) ----
    spmm_kernel<<<gHW, TB>>>(nullptr, BUF_G2, BUF_T1);
    spmm_kernel<<<gHW, TB>>>(nullptr, BUF_T1, BUF_T2);
    dense1_kernel<<<gW, TB>>>(W2, out);
}

// round 11
// speedup vs baseline: 1.2741x; 1.0782x over previous
#include <cuda_runtime.h>
#include <stdint.h>

// ============================================================================
// TAGNet: 3x TAGConv(K=2) with dropout(0.5, jax threefry key 42) + PReLU
// N=50000 nodes, E=800000 edges, 64 -> 64 -> 64 -> 1
// R11: layer-2 projection-first (A and W commute) -> two 1-wide SpMMs
//      instead of two 64-wide SpMMs. Parallel scan, fused act (from R7).
// ============================================================================

#define NN 50000
#define EE 800000
#define FD 64

#define SB 1024
#define NSB ((NN + SB - 1) / SB)   // 49

// ---------------- device scratch (static: no allocations allowed) ----------
__device__ float g_deg[NN];
__device__ float g_dinv[NN];
__device__ int   g_cnt[NN];
__device__ int   g_rowptr[NN + 1];
__device__ int   g_bsum[NSB];
__device__ int   g_boff[NSB];
__device__ int2  g_edge[EE];     // (src, w-as-int) per col-sorted edge
__device__ float g_T1[NN * FD];
__device__ float g_T2[NN * FD];
__device__ float g_G1[NN * FD];
__device__ float g_G2[NN * FD];
__device__ float g_s0[NN];       // G2 @ W2[0]
__device__ float g_s1[NN];       // G2 @ W2[1]
__device__ float g_s2[NN];       // G2 @ W2[2]
__device__ float g_u[NN];        // s1 + A s2

#define BUF_T1 1
#define BUF_T2 2
#define BUF_G1 3
#define BUF_G2 4
__device__ __forceinline__ float* buf_sel(int s) {
    switch (s) {
        case BUF_T1: return g_T1;
        case BUF_T2: return g_T2;
        case BUF_G1: return g_G1;
        default:     return g_G2;
    }
}

// small (N-float) vector selector for the 1-wide pipeline
#define VEC_S0 0
#define VEC_S1 1
#define VEC_S2 2
#define VEC_U  3
__device__ __forceinline__ float* vec_sel(int s) {
    switch (s) {
        case VEC_S0: return g_s0;
        case VEC_S1: return g_s1;
        case VEC_S2: return g_s2;
        default:     return g_u;
    }
}

// ---------------- Threefry-2x32 (JAX-compatible, 20 rounds) ----------------
__host__ __device__ __forceinline__ unsigned tf_rotl(unsigned x, int d) {
    return (x << d) | (x >> (32 - d));
}

__host__ __device__ __forceinline__ void tf2x32(unsigned k0, unsigned k1,
                                                unsigned x0, unsigned x1,
                                                unsigned& o0, unsigned& o1) {
    const unsigned ks2 = k0 ^ k1 ^ 0x1BD11BDAu;
    unsigned v0 = x0 + k0;
    unsigned v1 = x1 + k1;
#define TF_R4(a, b, c, d)                                   \
    v0 += v1; v1 = tf_rotl(v1, a); v1 ^= v0;                \
    v0 += v1; v1 = tf_rotl(v1, b); v1 ^= v0;                \
    v0 += v1; v1 = tf_rotl(v1, c); v1 ^= v0;                \
    v0 += v1; v1 = tf_rotl(v1, d); v1 ^= v0;
    TF_R4(13, 15, 26, 6);  v0 += k1;  v1 += ks2 + 1u;
    TF_R4(17, 29, 16, 24); v0 += ks2; v1 += k0 + 2u;
    TF_R4(13, 15, 26, 6);  v0 += k0;  v1 += k1 + 3u;
    TF_R4(17, 29, 16, 24); v0 += k1;  v1 += ks2 + 4u;
    TF_R4(13, 15, 26, 6);  v0 += ks2; v1 += k0 + 5u;
#undef TF_R4
    o0 = v0;
    o1 = v1;
}

// dropout(0.5) + PReLU on a single value at flat index i
__device__ __forceinline__ float act_apply(float h, unsigned i,
                                           unsigned k0, unsigned k1, float a) {
    unsigned b1, b2;
    tf2x32(k0, k1, 0u, i, b1, b2);
    unsigned bits = b1 ^ b2;
    h = (bits & 0x80000000u) ? 0.0f : 2.0f * h;
    return (h >= 0.0f) ? h : a * h;
}

// ---------------- graph preprocessing ---------------------------------------
__device__ __forceinline__ int clamp_node(int v) {
    return (v < 0) ? 0 : ((v >= NN) ? NN - 1 : v);
}

__global__ void zero_kernel() {
    int i = blockIdx.x * blockDim.x + threadIdx.x;
    if (i < NN) {
        g_deg[i] = 0.0f;
        g_cnt[i] = 0;
    }
}

__global__ void deg_kernel(const int* __restrict__ ei,
                           const float* __restrict__ ea) {
    int e = blockIdx.x * blockDim.x + threadIdx.x;
    if (e >= EE) return;
    int c = clamp_node(ei[EE + e]);  // col = target
    atomicAdd(&g_deg[c], ea[e]);
    atomicAdd(&g_cnt[c], 1);
}

__global__ void dinv_kernel() {
    int n = blockIdx.x * blockDim.x + threadIdx.x;
    if (n >= NN) return;
    float d = g_deg[n];
    g_dinv[n] = (d > 0.0f) ? rsqrtf(fmaxf(d, 1e-12f)) : 0.0f;
}

// ---- parallel exclusive scan of g_cnt -> g_rowptr (3 kernels) ----
__global__ void scan1_kernel() {  // grid NSB, block SB: block sums
    __shared__ int sh[SB];
    int i = blockIdx.x * SB + threadIdx.x;
    sh[threadIdx.x] = (i < NN) ? g_cnt[i] : 0;
    __syncthreads();
    for (int off = SB / 2; off; off >>= 1) {
        if (threadIdx.x < off) sh[threadIdx.x] += sh[threadIdx.x + off];
        __syncthreads();
    }
    if (threadIdx.x == 0) g_bsum[blockIdx.x] = sh[0];
}

__global__ void scan2_kernel() {  // 1 block of 64: scan block sums
    __shared__ int sh[64];
    int t = threadIdx.x;
    int v = (t < NSB) ? g_bsum[t] : 0;
    sh[t] = v;
    __syncthreads();
    for (int off = 1; off < 64; off <<= 1) {
        int u = (t >= off) ? sh[t - off] : 0;
        __syncthreads();
        sh[t] += u;
        __syncthreads();
    }
    if (t < NSB) g_boff[t] = sh[t] - v;   // exclusive
    if (t == 63) g_rowptr[NN] = sh[63];   // total (= EE)
}

__global__ void scan3_kernel() {  // grid NSB, block SB: local scan + offset
    __shared__ int sh[SB];
    int i = blockIdx.x * SB + threadIdx.x;
    int v = (i < NN) ? g_cnt[i] : 0;
    sh[threadIdx.x] = v;
    __syncthreads();
    for (int off = 1; off < SB; off <<= 1) {
        int u = (threadIdx.x >= off) ? sh[threadIdx.x - off] : 0;
        __syncthreads();
        sh[threadIdx.x] += u;
        __syncthreads();
    }
    if (i < NN) {
        g_rowptr[i] = g_boff[blockIdx.x] + sh[threadIdx.x] - v;  // exclusive
        g_cnt[i] = 0;
    }
}

__global__ void sort_kernel(const int* __restrict__ ei,
                            const float* __restrict__ ea) {
    int e = blockIdx.x * blockDim.x + threadIdx.x;
    if (e >= EE) return;
    int r = clamp_node(ei[e]);
    int c = clamp_node(ei[EE + e]);
    int p = g_rowptr[c] + atomicAdd(&g_cnt[c], 1);
    if (p < 0) p = 0;
    if (p >= EE) p = EE - 1;
    float w = g_dinv[r] * ea[e] * g_dinv[c];
    g_edge[p] = make_int2(r, __float_as_int(w));
}

// ---------------- SpMM: half-warp (16 lanes) per node, float4 per lane -----
__global__ void spmm_kernel(const float* __restrict__ hin_ext, int in_sel,
                            int out_sel) {
    int hw = (blockIdx.x * blockDim.x + threadIdx.x) >> 4;  // node
    int lane = threadIdx.x & 15;
    if (hw >= NN) return;
    const float* __restrict__ hin = (in_sel == 0) ? hin_ext : buf_sel(in_sel);
    const float4* __restrict__ hin4 = (const float4*)hin;
    float4* __restrict__ hout4 = (float4*)buf_sel(out_sel);
    int s = g_rowptr[hw];
    int e = g_rowptr[hw + 1];
    float4 acc = make_float4(0.f, 0.f, 0.f, 0.f);
    int j = s;
    for (; j + 4 <= e; j += 4) {
        int2 e0 = g_edge[j];
        int2 e1 = g_edge[j + 1];
        int2 e2 = g_edge[j + 2];
        int2 e3 = g_edge[j + 3];
        float4 v0 = __ldg(&hin4[e0.x * 16 + lane]);
        float4 v1 = __ldg(&hin4[e1.x * 16 + lane]);
        float4 v2 = __ldg(&hin4[e2.x * 16 + lane]);
        float4 v3 = __ldg(&hin4[e3.x * 16 + lane]);
        float w0 = __int_as_float(e0.y);
        float w1 = __int_as_float(e1.y);
        float w2 = __int_as_float(e2.y);
        float w3 = __int_as_float(e3.y);
        acc.x += w0 * v0.x; acc.y += w0 * v0.y; acc.z += w0 * v0.z; acc.w += w0 * v0.w;
        acc.x += w1 * v1.x; acc.y += w1 * v1.y; acc.z += w1 * v1.z; acc.w += w1 * v1.w;
        acc.x += w2 * v2.x; acc.y += w2 * v2.y; acc.z += w2 * v2.z; acc.w += w2 * v2.w;
        acc.x += w3 * v3.x; acc.y += w3 * v3.y; acc.z += w3 * v3.z; acc.w += w3 * v3.w;
    }
    for (; j < e; j++) {
        int2 ed = g_edge[j];
        float w = __int_as_float(ed.y);
        float4 v = __ldg(&hin4[ed.x * 16 + lane]);
        acc.x += w * v.x; acc.y += w * v.y; acc.z += w * v.z; acc.w += w * v.w;
    }
    hout4[hw * 16 + lane] = acc;
}

// ---------------- 1-wide SpMM: out[n] = add[n] + sum w_e * vin[src_e] -------
// thread per node; out goes to vec_sel(out_sel) or external (out_sel<0).
__global__ void spmm1_kernel(int in_sel, int add_sel, int out_sel,
                             float* __restrict__ out_ext) {
    int n = blockIdx.x * blockDim.x + threadIdx.x;
    if (n >= NN) return;
    const float* __restrict__ vin = vec_sel(in_sel);
    float* __restrict__ vout = (out_sel < 0) ? out_ext : vec_sel(out_sel);
    int s = g_rowptr[n];
    int e = g_rowptr[n + 1];
    float acc = 0.0f;
    int j = s;
    for (; j + 4 <= e; j += 4) {
        int2 e0 = g_edge[j];
        int2 e1 = g_edge[j + 1];
        int2 e2 = g_edge[j + 2];
        int2 e3 = g_edge[j + 3];
        float v0 = __ldg(&vin[e0.x]);
        float v1 = __ldg(&vin[e1.x]);
        float v2 = __ldg(&vin[e2.x]);
        float v3 = __ldg(&vin[e3.x]);
        acc += __int_as_float(e0.y) * v0 + __int_as_float(e1.y) * v1
             + __int_as_float(e2.y) * v2 + __int_as_float(e3.y) * v3;
    }
    for (; j < e; j++) {
        int2 ed = g_edge[j];
        acc += __int_as_float(ed.y) * __ldg(&vin[ed.x]);
    }
    vout[n] = vec_sel(add_sel)[n] + acc;
}

// ---------------- fused dense + optional dropout/PReLU ----------------------
// out = H@W[0] + T1@W[1] + T2@W[2]; if apply_act: dropout(threefry)+PReLU.
#define NPB 16  // nodes per block (256 threads: 16 nodes x 16 threads x 4 cols)
__global__ void dense64_kernel(const float* __restrict__ H_ext, int h_sel,
                               const float* __restrict__ W,  // (3,64,64)
                               int out_sel, int apply_act,
                               const float* __restrict__ a_ptr,
                               unsigned k0, unsigned k1) {
    __shared__ float sW[3 * 64 * 64];
    for (int i = threadIdx.x; i < 3 * 64 * 64; i += 256) sW[i] = W[i];
    __syncthreads();
    int node = blockIdx.x * NPB + (threadIdx.x >> 4);
    int c0 = (threadIdx.x & 15) * 4;
    if (node >= NN) return;
    const float* __restrict__ H = (h_sel == 0) ? H_ext : buf_sel(h_sel);
    float* __restrict__ out = buf_sel(out_sel);
    const float* h  = H    + node * FD;
    const float* t1 = g_T1 + node * FD;
    const float* t2 = g_T2 + node * FD;
    float a0 = 0, a1 = 0, a2 = 0, a3 = 0;
#pragma unroll 4
    for (int i = 0; i < 64; i++) {
        float hv  = __ldg(&h[i]);
        float t1v = t1[i];
        float t2v = t2[i];
        float4 w0 = *(const float4*)&sW[(0 * 64 + i) * 64 + c0];
        float4 w1 = *(const float4*)&sW[(1 * 64 + i) * 64 + c0];
        float4 w2 = *(const float4*)&sW[(2 * 64 + i) * 64 + c0];
        a0 += hv * w0.x + t1v * w1.x + t2v * w2.x;
        a1 += hv * w0.y + t1v * w1.y + t2v * w2.y;
        a2 += hv * w0.z + t1v * w1.z + t2v * w2.z;
        a3 += hv * w0.w + t1v * w1.w + t2v * w2.w;
    }
    if (apply_act) {
        unsigned base = (unsigned)(node * FD + c0);
        float a = __ldg(&a_ptr[0]);
        a0 = act_apply(a0, base + 0u, k0, k1, a);
        a1 = act_apply(a1, base + 1u, k0, k1, a);
        a2 = act_apply(a2, base + 2u, k0, k1, a);
        a3 = act_apply(a3, base + 3u, k0, k1, a);
    }
    *(float4*)&out[node * FD + c0] = make_float4(a0, a1, a2, a3);
}

// ---------------- 3-way projection: s_k[n] = G2[n,:] @ W2[k,:,0], k=0..2 ----
__global__ void proj3_kernel(const float* __restrict__ W) {  // (3,64,1)
    int warp = (blockIdx.x * blockDim.x + threadIdx.x) >> 5;
    int lane = threadIdx.x & 31;
    if (warp >= NN) return;
    int i0 = lane * 2;
    float2 g = *(const float2*)&g_G2[warp * FD + i0];
    float s0 = g.x * __ldg(&W[i0])       + g.y * __ldg(&W[i0 + 1]);
    float s1 = g.x * __ldg(&W[64 + i0])  + g.y * __ldg(&W[64 + i0 + 1]);
    float s2 = g.x * __ldg(&W[128 + i0]) + g.y * __ldg(&W[128 + i0 + 1]);
#pragma unroll
    for (int off = 16; off; off >>= 1) {
        s0 += __shfl_down_sync(0xFFFFFFFFu, s0, off);
        s1 += __shfl_down_sync(0xFFFFFFFFu, s1, off);
        s2 += __shfl_down_sync(0xFFFFFFFFu, s2, off);
    }
    if (lane == 0) {
        g_s0[warp] = s0;
        g_s1[warp] = s1;
        g_s2[warp] = s2;
    }
}

// ============================================================================
extern "C" void kernel_launch(void* const* d_in, const int* in_sizes, int n_in,
                              void* d_out, int out_size) {
    const float* x  = (const float*)d_in[0];
    const int*   ei = (const int*)d_in[1];     // int32: JAX x64-disabled
    const float* ea = (const float*)d_in[2];
    const float* W0 = (const float*)d_in[3];
    const float* W1 = (const float*)d_in[4];
    const float* W2 = (const float*)d_in[5];
    const float* a0 = (const float*)d_in[6];
    const float* a1 = (const float*)d_in[7];
    float* out = (float*)d_out;

    // host-side Threefry: dropout subkeys from jax.random.key(42) = (0, 42)
    unsigned dk0_0, dk0_1, dk1_0, dk1_1;
    tf2x32(0u, 42u, 0u, 0u, dk0_0, dk0_1);
    tf2x32(0u, 42u, 0u, 1u, dk1_0, dk1_1);

    const int TB = 256;
    const int gN  = (NN + TB - 1) / TB;
    const int gE  = (EE + TB - 1) / TB;
    const int gHW = (NN * 16 + TB - 1) / TB;   // half-warp per node
    const int gW  = (NN * 32 + TB - 1) / TB;   // warp per node
    const int gD  = (NN + NPB - 1) / NPB;

    // ---- graph preprocessing (CSR by target) ----
    zero_kernel<<<gN, TB>>>();
    deg_kernel<<<gE, TB>>>(ei, ea);
    dinv_kernel<<<gN, TB>>>();
    scan1_kernel<<<NSB, SB>>>();
    scan2_kernel<<<1, 64>>>();
    scan3_kernel<<<NSB, SB>>>();
    sort_kernel<<<gE, TB>>>(ei, ea);

    // ---- layer 0: x -> G1 ----
    spmm_kernel<<<gHW, TB>>>(x, 0, BUF_T1);
    spmm_kernel<<<gHW, TB>>>(nullptr, BUF_T1, BUF_T2);
    dense64_kernel<<<gD, TB>>>(x, 0, W0, BUF_G1, 1, a0, dk0_0, dk0_1);

    // ---- layer 1: G1 -> G2 ----
    spmm_kernel<<<gHW, TB>>>(nullptr, BUF_G1, BUF_T1);
    spmm_kernel<<<gHW, TB>>>(nullptr, BUF_T1, BUF_T2);
    dense64_kernel<<<gD, TB>>>(nullptr, BUF_G1, W1, BUF_G2, 1, a1, dk1_0, dk1_1);

    // ---- layer 2 (projection-first): out = s0 + A(s1 + A s2) ----
    proj3_kernel<<<gW, TB>>>(W2);
    spmm1_kernel<<<gN, TB>>>(VEC_S2, VEC_S1, VEC_U, nullptr);  // u = s1 + A s2
    spmm1_kernel<<<gN, TB>>>(VEC_U, VEC_S0, -1, out);          // out = s0 + A u
}

// round 13
// speedup vs baseline: 1.5441x; 1.2119x over previous
#include <cuda_runtime.h>
#include <cuda_fp16.h>
#include <stdint.h>

// ============================================================================
// TAGNet: 3x TAGConv(K=2) with dropout(0.5, jax threefry key 42) + PReLU
// N=50000 nodes, E=800000 edges, 64 -> 64 -> 64 -> 1
// R12: fp16 feature storage (fp32 accumulation) -> halves SpMM gather traffic.
//      Layer-2 projection-first; parallel scan; fused dropout+PReLU.
// ============================================================================

#define NN 50000
#define EE 800000
#define FD 64

#define SB 1024
#define NSB ((NN + SB - 1) / SB)   // 49

// ---------------- device scratch (static: no allocations allowed) ----------
__device__ float  g_deg[NN];
__device__ float  g_dinv[NN];
__device__ int    g_cnt[NN];
__device__ int    g_rowptr[NN + 1];
__device__ int    g_bsum[NSB];
__device__ int    g_boff[NSB];
__device__ int2   g_edge[EE];     // (src, w-as-int) per col-sorted edge
__device__ __half g_Xh[NN * FD];
__device__ __half g_T1h[NN * FD];
__device__ __half g_T2h[NN * FD];
__device__ __half g_G1h[NN * FD];
__device__ __half g_G2h[NN * FD];
__device__ float  g_s0[NN];       // G2 @ W2[0]
__device__ float  g_s1[NN];       // G2 @ W2[1]
__device__ float  g_s2[NN];       // G2 @ W2[2]
__device__ float  g_u[NN];        // s1 + A s2

#define HB_X  0
#define HB_T1 1
#define HB_T2 2
#define HB_G1 3
#define HB_G2 4
__device__ __forceinline__ __half* hbuf_sel(int s) {
    switch (s) {
        case HB_X:  return g_Xh;
        case HB_T1: return g_T1h;
        case HB_T2: return g_T2h;
        case HB_G1: return g_G1h;
        default:    return g_G2h;
    }
}

#define VEC_S0 0
#define VEC_S1 1
#define VEC_S2 2
#define VEC_U  3
__device__ __forceinline__ float* vec_sel(int s) {
    switch (s) {
        case VEC_S0: return g_s0;
        case VEC_S1: return g_s1;
        case VEC_S2: return g_s2;
        default:     return g_u;
    }
}

// ---------------- Threefry-2x32 (JAX-compatible, 20 rounds) ----------------
__host__ __device__ __forceinline__ unsigned tf_rotl(unsigned x, int d) {
    return (x << d) | (x >> (32 - d));
}

__host__ __device__ __forceinline__ void tf2x32(unsigned k0, unsigned k1,
                                                unsigned x0, unsigned x1,
                                                unsigned& o0, unsigned& o1) {
    const unsigned ks2 = k0 ^ k1 ^ 0x1BD11BDAu;
    unsigned v0 = x0 + k0;
    unsigned v1 = x1 + k1;
#define TF_R4(a, b, c, d)                                   \
    v0 += v1; v1 = tf_rotl(v1, a); v1 ^= v0;                \
    v0 += v1; v1 = tf_rotl(v1, b); v1 ^= v0;                \
    v0 += v1; v1 = tf_rotl(v1, c); v1 ^= v0;                \
    v0 += v1; v1 = tf_rotl(v1, d); v1 ^= v0;
    TF_R4(13, 15, 26, 6);  v0 += k1;  v1 += ks2 + 1u;
    TF_R4(17, 29, 16, 24); v0 += ks2; v1 += k0 + 2u;
    TF_R4(13, 15, 26, 6);  v0 += k0;  v1 += k1 + 3u;
    TF_R4(17, 29, 16, 24); v0 += k1;  v1 += ks2 + 4u;
    TF_R4(13, 15, 26, 6);  v0 += ks2; v1 += k0 + 5u;
#undef TF_R4
    o0 = v0;
    o1 = v1;
}

// dropout(0.5) + PReLU on a single value at flat index i
__device__ __forceinline__ float act_apply(float h, unsigned i,
                                           unsigned k0, unsigned k1, float a) {
    unsigned b1, b2;
    tf2x32(k0, k1, 0u, i, b1, b2);
    unsigned bits = b1 ^ b2;
    h = (bits & 0x80000000u) ? 0.0f : 2.0f * h;
    return (h >= 0.0f) ? h : a * h;
}

// ---------------- graph preprocessing ---------------------------------------
__device__ __forceinline__ int clamp_node(int v) {
    return (v < 0) ? 0 : ((v >= NN) ? NN - 1 : v);
}

__global__ void zero_kernel() {
    int i = blockIdx.x * blockDim.x + threadIdx.x;
    if (i < NN) {
        g_deg[i] = 0.0f;
        g_cnt[i] = 0;
    }
}

__global__ void deg_kernel(const int* __restrict__ ei,
                           const float* __restrict__ ea) {
    int e = blockIdx.x * blockDim.x + threadIdx.x;
    if (e >= EE) return;
    int c = clamp_node(ei[EE + e]);  // col = target
    atomicAdd(&g_deg[c], ea[e]);
    atomicAdd(&g_cnt[c], 1);
}

__global__ void dinv_kernel() {
    int n = blockIdx.x * blockDim.x + threadIdx.x;
    if (n >= NN) return;
    float d = g_deg[n];
    g_dinv[n] = (d > 0.0f) ? rsqrtf(fmaxf(d, 1e-12f)) : 0.0f;
}

// ---- parallel exclusive scan of g_cnt -> g_rowptr (3 kernels) ----
__global__ void scan1_kernel() {  // grid NSB, block SB: block sums
    __shared__ int sh[SB];
    int i = blockIdx.x * SB + threadIdx.x;
    sh[threadIdx.x] = (i < NN) ? g_cnt[i] : 0;
    __syncthreads();
    for (int off = SB / 2; off; off >>= 1) {
        if (threadIdx.x < off) sh[threadIdx.x] += sh[threadIdx.x + off];
        __syncthreads();
    }
    if (threadIdx.x == 0) g_bsum[blockIdx.x] = sh[0];
}

__global__ void scan2_kernel() {  // 1 block of 64: scan block sums
    __shared__ int sh[64];
    int t = threadIdx.x;
    int v = (t < NSB) ? g_bsum[t] : 0;
    sh[t] = v;
    __syncthreads();
    for (int off = 1; off < 64; off <<= 1) {
        int u = (t >= off) ? sh[t - off] : 0;
        __syncthreads();
        sh[t] += u;
        __syncthreads();
    }
    if (t < NSB) g_boff[t] = sh[t] - v;   // exclusive
    if (t == 63) g_rowptr[NN] = sh[63];   // total (= EE)
}

__global__ void scan3_kernel() {  // grid NSB, block SB: local scan + offset
    __shared__ int sh[SB];
    int i = blockIdx.x * SB + threadIdx.x;
    int v = (i < NN) ? g_cnt[i] : 0;
    sh[threadIdx.x] = v;
    __syncthreads();
    for (int off = 1; off < SB; off <<= 1) {
        int u = (threadIdx.x >= off) ? sh[threadIdx.x - off] : 0;
        __syncthreads();
        sh[threadIdx.x] += u;
        __syncthreads();
    }
    if (i < NN) {
        g_rowptr[i] = g_boff[blockIdx.x] + sh[threadIdx.x] - v;  // exclusive
        g_cnt[i] = 0;
    }
}

__global__ void sort_kernel(const int* __restrict__ ei,
                            const float* __restrict__ ea) {
    int e = blockIdx.x * blockDim.x + threadIdx.x;
    if (e >= EE) return;
    int r = clamp_node(ei[e]);
    int c = clamp_node(ei[EE + e]);
    int p = g_rowptr[c] + atomicAdd(&g_cnt[c], 1);
    if (p < 0) p = 0;
    if (p >= EE) p = EE - 1;
    float w = g_dinv[r] * ea[e] * g_dinv[c];
    g_edge[p] = make_int2(r, __float_as_int(w));
}

// ---------------- x (fp32) -> Xh (fp16) -------------------------------------
__global__ void cvt_kernel(const float* __restrict__ x) {
    int i = blockIdx.x * blockDim.x + threadIdx.x;
    if (i >= NN * (FD / 2)) return;
    float2 v = ((const float2*)x)[i];
    ((__half2*)g_Xh)[i] = __float22half2_rn(v);
}

// ---------------- SpMM: 8 lanes per node, uint4 (8 halves) per lane --------
__device__ __forceinline__ void hfma8(float* acc, uint4 v, float w) {
    float2 f;
    f = __half22float2(*(__half2*)&v.x); acc[0] += w * f.x; acc[1] += w * f.y;
    f = __half22float2(*(__half2*)&v.y); acc[2] += w * f.x; acc[3] += w * f.y;
    f = __half22float2(*(__half2*)&v.z); acc[4] += w * f.x; acc[5] += w * f.y;
    f = __half22float2(*(__half2*)&v.w); acc[6] += w * f.x; acc[7] += w * f.y;
}

__global__ void spmmh_kernel(int in_sel, int out_sel) {
    int t = blockIdx.x * blockDim.x + threadIdx.x;
    int n = t >> 3;            // node
    int lane = t & 7;
    if (n >= NN) return;
    const uint4* __restrict__ hin = (const uint4*)hbuf_sel(in_sel);  // 8/row
    uint4* __restrict__ hout = (uint4*)hbuf_sel(out_sel);
    int s = g_rowptr[n];
    int e = g_rowptr[n + 1];
    float acc[8] = {0.f, 0.f, 0.f, 0.f, 0.f, 0.f, 0.f, 0.f};
    int j = s;
    for (; j + 4 <= e; j += 4) {
        int2 e0 = g_edge[j];
        int2 e1 = g_edge[j + 1];
        int2 e2 = g_edge[j + 2];
        int2 e3 = g_edge[j + 3];
        uint4 v0 = __ldg(&hin[e0.x * 8 + lane]);
        uint4 v1 = __ldg(&hin[e1.x * 8 + lane]);
        uint4 v2 = __ldg(&hin[e2.x * 8 + lane]);
        uint4 v3 = __ldg(&hin[e3.x * 8 + lane]);
        hfma8(acc, v0, __int_as_float(e0.y));
        hfma8(acc, v1, __int_as_float(e1.y));
        hfma8(acc, v2, __int_as_float(e2.y));
        hfma8(acc, v3, __int_as_float(e3.y));
    }
    for (; j < e; j++) {
        int2 ed = g_edge[j];
        uint4 v = __ldg(&hin[ed.x * 8 + lane]);
        hfma8(acc, v, __int_as_float(ed.y));
    }
    uint4 o;
    *(__half2*)&o.x = __floats2half2_rn(acc[0], acc[1]);
    *(__half2*)&o.y = __floats2half2_rn(acc[2], acc[3]);
    *(__half2*)&o.z = __floats2half2_rn(acc[4], acc[5]);
    *(__half2*)&o.w = __floats2half2_rn(acc[6], acc[7]);
    hout[n * 8 + lane] = o;
}

// ---------------- fused dense + dropout/PReLU (half in, half out) ----------
// out = H@W[0] + T1h@W[1] + T2h@W[2]; then dropout(threefry)+PReLU.
#define NPB 16  // nodes per block (256 threads: 16 nodes x 16 threads x 4 cols)
__global__ void dense64_kernel(int h_sel,
                               const float* __restrict__ W,  // (3,64,64)
                               int out_sel,
                               const float* __restrict__ a_ptr,
                               unsigned k0, unsigned k1) {
    __shared__ float sW[3 * 64 * 64];
    for (int i = threadIdx.x; i < 3 * 64 * 64; i += 256) sW[i] = W[i];
    __syncthreads();
    int node = blockIdx.x * NPB + (threadIdx.x >> 4);
    int c0 = (threadIdx.x & 15) * 4;
    if (node >= NN) return;
    const __half2* __restrict__ h  = (const __half2*)hbuf_sel(h_sel) + node * 32;
    const __half2* __restrict__ t1 = (const __half2*)g_T1h + node * 32;
    const __half2* __restrict__ t2 = (const __half2*)g_T2h + node * 32;
    float a0 = 0, a1 = 0, a2 = 0, a3 = 0;
#pragma unroll 4
    for (int i = 0; i < 32; i++) {
        float2 hv  = __half22float2(__ldg(&h[i]));
        float2 t1v = __half22float2(__ldg(&t1[i]));
        float2 t2v = __half22float2(__ldg(&t2[i]));
        int ka = 2 * i, kb = 2 * i + 1;
        float4 w0a = *(const float4*)&sW[(0 * 64 + ka) * 64 + c0];
        float4 w0b = *(const float4*)&sW[(0 * 64 + kb) * 64 + c0];
        float4 w1a = *(const float4*)&sW[(1 * 64 + ka) * 64 + c0];
        float4 w1b = *(const float4*)&sW[(1 * 64 + kb) * 64 + c0];
        float4 w2a = *(const float4*)&sW[(2 * 64 + ka) * 64 + c0];
        float4 w2b = *(const float4*)&sW[(2 * 64 + kb) * 64 + c0];
        a0 += hv.x * w0a.x + hv.y * w0b.x + t1v.x * w1a.x + t1v.y * w1b.x
            + t2v.x * w2a.x + t2v.y * w2b.x;
        a1 += hv.x * w0a.y + hv.y * w0b.y + t1v.x * w1a.y + t1v.y * w1b.y
            + t2v.x * w2a.y + t2v.y * w2b.y;
        a2 += hv.x * w0a.z + hv.y * w0b.z + t1v.x * w1a.z + t1v.y * w1b.z
            + t2v.x * w2a.z + t2v.y * w2b.z;
        a3 += hv.x * w0a.w + hv.y * w0b.w + t1v.x * w1a.w + t1v.y * w1b.w
            + t2v.x * w2a.w + t2v.y * w2b.w;
    }
    unsigned base = (unsigned)(node * FD + c0);
    float a = __ldg(&a_ptr[0]);
    a0 = act_apply(a0, base + 0u, k0, k1, a);
    a1 = act_apply(a1, base + 1u, k0, k1, a);
    a2 = act_apply(a2, base + 2u, k0, k1, a);
    a3 = act_apply(a3, base + 3u, k0, k1, a);
    __half2* outp = (__half2*)hbuf_sel(out_sel) + node * 32 + c0 / 2;
    outp[0] = __floats2half2_rn(a0, a1);
    outp[1] = __floats2half2_rn(a2, a3);
}

// ---------------- 3-way projection: s_k[n] = G2h[n,:] @ W2[k,:,0] ----------
__global__ void proj3_kernel(const float* __restrict__ W) {  // (3,64,1)
    int warp = (blockIdx.x * blockDim.x + threadIdx.x) >> 5;
    int lane = threadIdx.x & 31;
    if (warp >= NN) return;
    int i0 = lane * 2;
    float2 g = __half22float2(((const __half2*)g_G2h)[warp * 32 + lane]);
    float s0 = g.x * __ldg(&W[i0])       + g.y * __ldg(&W[i0 + 1]);
    float s1 = g.x * __ldg(&W[64 + i0])  + g.y * __ldg(&W[64 + i0 + 1]);
    float s2 = g.x * __ldg(&W[128 + i0]) + g.y * __ldg(&W[128 + i0 + 1]);
#pragma unroll
    for (int off = 16; off; off >>= 1) {
        s0 += __shfl_down_sync(0xFFFFFFFFu, s0, off);
        s1 += __shfl_down_sync(0xFFFFFFFFu, s1, off);
        s2 += __shfl_down_sync(0xFFFFFFFFu, s2, off);
    }
    if (lane == 0) {
        g_s0[warp] = s0;
        g_s1[warp] = s1;
        g_s2[warp] = s2;
    }
}

// ---------------- 1-wide SpMM: out[n] = add[n] + sum w_e * vin[src_e] -------
__global__ void spmm1_kernel(int in_sel, int add_sel, int out_sel,
                             float* __restrict__ out_ext) {
    int n = blockIdx.x * blockDim.x + threadIdx.x;
    if (n >= NN) return;
    const float* __restrict__ vin = vec_sel(in_sel);
    float* __restrict__ vout = (out_sel < 0) ? out_ext : vec_sel(out_sel);
    int s = g_rowptr[n];
    int e = g_rowptr[n + 1];
    float acc = 0.0f;
    int j = s;
    for (; j + 4 <= e; j += 4) {
        int2 e0 = g_edge[j];
        int2 e1 = g_edge[j + 1];
        int2 e2 = g_edge[j + 2];
        int2 e3 = g_edge[j + 3];
        float v0 = __ldg(&vin[e0.x]);
        float v1 = __ldg(&vin[e1.x]);
        float v2 = __ldg(&vin[e2.x]);
        float v3 = __ldg(&vin[e3.x]);
        acc += __int_as_float(e0.y) * v0 + __int_as_float(e1.y) * v1
             + __int_as_float(e2.y) * v2 + __int_as_float(e3.y) * v3;
    }
    for (; j < e; j++) {
        int2 ed = g_edge[j];
        acc += __int_as_float(ed.y) * __ldg(&vin[ed.x]);
    }
    vout[n] = vec_sel(add_sel)[n] + acc;
}

// ============================================================================
extern "C" void kernel_launch(void* const* d_in, const int* in_sizes, int n_in,
                              void* d_out, int out_size) {
    const float* x  = (const float*)d_in[0];
    const int*   ei = (const int*)d_in[1];     // int32: JAX x64-disabled
    const float* ea = (const float*)d_in[2];
    const float* W0 = (const float*)d_in[3];
    const float* W1 = (const float*)d_in[4];
    const float* W2 = (const float*)d_in[5];
    const float* a0 = (const float*)d_in[6];
    const float* a1 = (const float*)d_in[7];
    float* out = (float*)d_out;

    // host-side Threefry: dropout subkeys from jax.random.key(42) = (0, 42)
    unsigned dk0_0, dk0_1, dk1_0, dk1_1;
    tf2x32(0u, 42u, 0u, 0u, dk0_0, dk0_1);
    tf2x32(0u, 42u, 0u, 1u, dk1_0, dk1_1);

    const int TB = 256;
    const int gN  = (NN + TB - 1) / TB;
    const int gE  = (EE + TB - 1) / TB;
    const int gS  = (NN * 8 + TB - 1) / TB;    // 8 lanes per node (spmmh)
    const int gW  = (NN * 32 + TB - 1) / TB;   // warp per node (proj3)
    const int gC  = (NN * (FD / 2) + TB - 1) / TB;
    const int gD  = (NN + NPB - 1) / NPB;

    // ---- graph preprocessing (CSR by target) ----
    zero_kernel<<<gN, TB>>>();
    deg_kernel<<<gE, TB>>>(ei, ea);
    dinv_kernel<<<gN, TB>>>();
    scan1_kernel<<<NSB, SB>>>();
    scan2_kernel<<<1, 64>>>();
    scan3_kernel<<<NSB, SB>>>();
    sort_kernel<<<gE, TB>>>(ei, ea);
    cvt_kernel<<<gC, TB>>>(x);

    // ---- layer 0: Xh -> G1h ----
    spmmh_kernel<<<gS, TB>>>(HB_X, HB_T1);
    spmmh_kernel<<<gS, TB>>>(HB_T1, HB_T2);
    dense64_kernel<<<gD, TB>>>(HB_X, W0, HB_G1, a0, dk0_0, dk0_1);

    // ---- layer 1: G1h -> G2h ----
    spmmh_kernel<<<gS, TB>>>(HB_G1, HB_T1);
    spmmh_kernel<<<gS, TB>>>(HB_T1, HB_T2);
    dense64_kernel<<<gD, TB>>>(HB_G1, W1, HB_G2, a1, dk1_0, dk1_1);

    // ---- layer 2 (projection-first): out = s0 + A(s1 + A s2) ----
    proj3_kernel<<<gW, TB>>>(W2);
    spmm1_kernel<<<gN, TB>>>(VEC_S2, VEC_S1, VEC_U, nullptr);  // u = s1 + A s2
    spmm1_kernel<<<gN, TB>>>(VEC_U, VEC_S0, -1, out);          // out = s0 + A u
}

// round 16
// speedup vs baseline: 1.9927x; 1.2905x over previous
#include <cuda_runtime.h>
#include <cuda_fp16.h>
#include <stdint.h>

// ============================================================================
// TAGNet: 3x TAGConv(K=2) with dropout(0.5, jax threefry key 42) + PReLU
// N=50000 nodes, E=800000 edges, 64 -> 64 -> 64 -> 1
// R14: dense64 register-tiled 4 nodes/thread (LDS-crossbar was binding).
//      fp16 features, layer-2 projection-first, parallel scan, fused act.
// ============================================================================

#define NN 50000
#define EE 800000
#define FD 64

#define SB 1024
#define NSB ((NN + SB - 1) / SB)   // 49

// ---------------- device scratch (static: no allocations allowed) ----------
__device__ float  g_deg[NN];
__device__ float  g_dinv[NN];
__device__ int    g_cnt[NN];
__device__ int    g_rowptr[NN + 1];
__device__ int    g_bsum[NSB];
__device__ int    g_boff[NSB];
__device__ int2   g_edge[EE];     // (src, w-as-int) per col-sorted edge
__device__ __half g_Xh[NN * FD];
__device__ __half g_T1h[NN * FD];
__device__ __half g_T2h[NN * FD];
__device__ __half g_G1h[NN * FD];
__device__ __half g_G2h[NN * FD];
__device__ float  g_s0[NN];       // G2 @ W2[0]
__device__ float  g_s1[NN];       // G2 @ W2[1]
__device__ float  g_s2[NN];       // G2 @ W2[2]
__device__ float  g_u[NN];        // s1 + A s2

#define HB_X  0
#define HB_T1 1
#define HB_T2 2
#define HB_G1 3
#define HB_G2 4
__device__ __forceinline__ __half* hbuf_sel(int s) {
    switch (s) {
        case HB_X:  return g_Xh;
        case HB_T1: return g_T1h;
        case HB_T2: return g_T2h;
        case HB_G1: return g_G1h;
        default:    return g_G2h;
    }
}

#define VEC_S0 0
#define VEC_S1 1
#define VEC_S2 2
#define VEC_U  3
__device__ __forceinline__ float* vec_sel(int s) {
    switch (s) {
        case VEC_S0: return g_s0;
        case VEC_S1: return g_s1;
        case VEC_S2: return g_s2;
        default:     return g_u;
    }
}

// ---------------- Threefry-2x32 (JAX-compatible, 20 rounds) ----------------
__host__ __device__ __forceinline__ unsigned tf_rotl(unsigned x, int d) {
    return (x << d) | (x >> (32 - d));
}

__host__ __device__ __forceinline__ void tf2x32(unsigned k0, unsigned k1,
                                                unsigned x0, unsigned x1,
                                                unsigned& o0, unsigned& o1) {
    const unsigned ks2 = k0 ^ k1 ^ 0x1BD11BDAu;
    unsigned v0 = x0 + k0;
    unsigned v1 = x1 + k1;
#define TF_R4(a, b, c, d)                                   \
    v0 += v1; v1 = tf_rotl(v1, a); v1 ^= v0;                \
    v0 += v1; v1 = tf_rotl(v1, b); v1 ^= v0;                \
    v0 += v1; v1 = tf_rotl(v1, c); v1 ^= v0;                \
    v0 += v1; v1 = tf_rotl(v1, d); v1 ^= v0;
    TF_R4(13, 15, 26, 6);  v0 += k1;  v1 += ks2 + 1u;
    TF_R4(17, 29, 16, 24); v0 += ks2; v1 += k0 + 2u;
    TF_R4(13, 15, 26, 6);  v0 += k0;  v1 += k1 + 3u;
    TF_R4(17, 29, 16, 24); v0 += k1;  v1 += ks2 + 4u;
    TF_R4(13, 15, 26, 6);  v0 += ks2; v1 += k0 + 5u;
#undef TF_R4
    o0 = v0;
    o1 = v1;
}

// dropout(0.5) + PReLU on a single value at flat index i
__device__ __forceinline__ float act_apply(float h, unsigned i,
                                           unsigned k0, unsigned k1, float a) {
    unsigned b1, b2;
    tf2x32(k0, k1, 0u, i, b1, b2);
    unsigned bits = b1 ^ b2;
    h = (bits & 0x80000000u) ? 0.0f : 2.0f * h;
    return (h >= 0.0f) ? h : a * h;
}

// ---------------- graph preprocessing ---------------------------------------
__device__ __forceinline__ int clamp_node(int v) {
    return (v < 0) ? 0 : ((v >= NN) ? NN - 1 : v);
}

__global__ void zero_kernel() {
    int i = blockIdx.x * blockDim.x + threadIdx.x;
    if (i < NN) {
        g_deg[i] = 0.0f;
        g_cnt[i] = 0;
    }
}

__global__ void deg_kernel(const int* __restrict__ ei,
                           const float* __restrict__ ea) {
    int e = blockIdx.x * blockDim.x + threadIdx.x;
    if (e >= EE) return;
    int c = clamp_node(ei[EE + e]);  // col = target
    atomicAdd(&g_deg[c], ea[e]);
    atomicAdd(&g_cnt[c], 1);
}

__global__ void dinv_kernel() {
    int n = blockIdx.x * blockDim.x + threadIdx.x;
    if (n >= NN) return;
    float d = g_deg[n];
    g_dinv[n] = (d > 0.0f) ? rsqrtf(fmaxf(d, 1e-12f)) : 0.0f;
}

// ---- parallel exclusive scan of g_cnt -> g_rowptr (3 kernels) ----
__global__ void scan1_kernel() {  // grid NSB, block SB: block sums
    __shared__ int sh[SB];
    int i = blockIdx.x * SB + threadIdx.x;
    sh[threadIdx.x] = (i < NN) ? g_cnt[i] : 0;
    __syncthreads();
    for (int off = SB / 2; off; off >>= 1) {
        if (threadIdx.x < off) sh[threadIdx.x] += sh[threadIdx.x + off];
        __syncthreads();
    }
    if (threadIdx.x == 0) g_bsum[blockIdx.x] = sh[0];
}

__global__ void scan2_kernel() {  // 1 block of 64: scan block sums
    __shared__ int sh[64];
    int t = threadIdx.x;
    int v = (t < NSB) ? g_bsum[t] : 0;
    sh[t] = v;
    __syncthreads();
    for (int off = 1; off < 64; off <<= 1) {
        int u = (t >= off) ? sh[t - off] : 0;
        __syncthreads();
        sh[t] += u;
        __syncthreads();
    }
    if (t < NSB) g_boff[t] = sh[t] - v;   // exclusive
    if (t == 63) g_rowptr[NN] = sh[63];   // total (= EE)
}

__global__ void scan3_kernel() {  // grid NSB, block SB: local scan + offset
    __shared__ int sh[SB];
    int i = blockIdx.x * SB + threadIdx.x;
    int v = (i < NN) ? g_cnt[i] : 0;
    sh[threadIdx.x] = v;
    __syncthreads();
    for (int off = 1; off < SB; off <<= 1) {
        int u = (threadIdx.x >= off) ? sh[threadIdx.x - off] : 0;
        __syncthreads();
        sh[threadIdx.x] += u;
        __syncthreads();
    }
    if (i < NN) {
        g_rowptr[i] = g_boff[blockIdx.x] + sh[threadIdx.x] - v;  // exclusive
        g_cnt[i] = 0;
    }
}

__global__ void sort_kernel(const int* __restrict__ ei,
                            const float* __restrict__ ea) {
    int e = blockIdx.x * blockDim.x + threadIdx.x;
    if (e >= EE) return;
    int r = clamp_node(ei[e]);
    int c = clamp_node(ei[EE + e]);
    int p = g_rowptr[c] + atomicAdd(&g_cnt[c], 1);
    if (p < 0) p = 0;
    if (p >= EE) p = EE - 1;
    float w = g_dinv[r] * ea[e] * g_dinv[c];
    g_edge[p] = make_int2(r, __float_as_int(w));
}

// ---------------- x (fp32) -> Xh (fp16) -------------------------------------
__global__ void cvt_kernel(const float* __restrict__ x) {
    int i = blockIdx.x * blockDim.x + threadIdx.x;
    if (i >= NN * (FD / 2)) return;
    float2 v = ((const float2*)x)[i];
    ((__half2*)g_Xh)[i] = __float22half2_rn(v);
}

// ---------------- SpMM: 8 lanes per node, uint4 (8 halves) per lane --------
__device__ __forceinline__ void hfma8(float* acc, uint4 v, float w) {
    float2 f;
    f = __half22float2(*(__half2*)&v.x); acc[0] += w * f.x; acc[1] += w * f.y;
    f = __half22float2(*(__half2*)&v.y); acc[2] += w * f.x; acc[3] += w * f.y;
    f = __half22float2(*(__half2*)&v.z); acc[4] += w * f.x; acc[5] += w * f.y;
    f = __half22float2(*(__half2*)&v.w); acc[6] += w * f.x; acc[7] += w * f.y;
}

__global__ void spmmh_kernel(int in_sel, int out_sel) {
    int t = blockIdx.x * blockDim.x + threadIdx.x;
    int n = t >> 3;            // node
    int lane = t & 7;
    if (n >= NN) return;
    const uint4* __restrict__ hin = (const uint4*)hbuf_sel(in_sel);  // 8/row
    uint4* __restrict__ hout = (uint4*)hbuf_sel(out_sel);
    int s = g_rowptr[n];
    int e = g_rowptr[n + 1];
    float acc[8] = {0.f, 0.f, 0.f, 0.f, 0.f, 0.f, 0.f, 0.f};
    int j = s;
    for (; j + 4 <= e; j += 4) {
        int2 e0 = g_edge[j];
        int2 e1 = g_edge[j + 1];
        int2 e2 = g_edge[j + 2];
        int2 e3 = g_edge[j + 3];
        uint4 v0 = __ldg(&hin[e0.x * 8 + lane]);
        uint4 v1 = __ldg(&hin[e1.x * 8 + lane]);
        uint4 v2 = __ldg(&hin[e2.x * 8 + lane]);
        uint4 v3 = __ldg(&hin[e3.x * 8 + lane]);
        hfma8(acc, v0, __int_as_float(e0.y));
        hfma8(acc, v1, __int_as_float(e1.y));
        hfma8(acc, v2, __int_as_float(e2.y));
        hfma8(acc, v3, __int_as_float(e3.y));
    }
    for (; j < e; j++) {
        int2 ed = g_edge[j];
        uint4 v = __ldg(&hin[ed.x * 8 + lane]);
        hfma8(acc, v, __int_as_float(ed.y));
    }
    uint4 o;
    *(__half2*)&o.x = __floats2half2_rn(acc[0], acc[1]);
    *(__half2*)&o.y = __floats2half2_rn(acc[2], acc[3]);
    *(__half2*)&o.z = __floats2half2_rn(acc[4], acc[5]);
    *(__half2*)&o.w = __floats2half2_rn(acc[6], acc[7]);
    hout[n * 8 + lane] = o;
}

// ---------------- fused dense + dropout/PReLU (half in, half out) ----------
// out = H@W[0] + T1h@W[1] + T2h@W[2]; then dropout(threefry)+PReLU.
// Register-tiled: each thread computes 4 nodes x 4 cols, so the smem weight
// loads (the former bottleneck: LDS crossbar) amortize over 4 nodes.
#define DNB 64  // nodes per block (256 threads: 16 slots x 4 nodes, 16 col-thr)
__global__ void dense64_kernel(int h_sel,
                               const float* __restrict__ W,  // (3,64,64)
                               int out_sel,
                               const float* __restrict__ a_ptr,
                               unsigned k0, unsigned k1) {
    __shared__ float sW[3 * 64 * 64];
    {
        const float4* Wv = (const float4*)W;
        float4* sWv = (float4*)sW;
        for (int i = threadIdx.x; i < 3 * 64 * 16; i += 256) sWv[i] = Wv[i];
    }
    __syncthreads();
    int slot = threadIdx.x >> 4;           // 0..15
    int c0 = (threadIdx.x & 15) * 4;       // output col base
    int n0 = blockIdx.x * DNB + slot * 4;  // 4 consecutive nodes
    int nn0 = clamp_node(n0);
    int nn1 = clamp_node(n0 + 1);
    int nn2 = clamp_node(n0 + 2);
    int nn3 = clamp_node(n0 + 3);
    const __half2* __restrict__ hb  = (const __half2*)hbuf_sel(h_sel);
    const __half2* __restrict__ t1b = (const __half2*)g_T1h;
    const __half2* __restrict__ t2b = (const __half2*)g_T2h;
    const __half2* h0 = hb + nn0 * 32, *h1 = hb + nn1 * 32,
                 * h2 = hb + nn2 * 32, *h3 = hb + nn3 * 32;
    const __half2* p0 = t1b + nn0 * 32, *p1 = t1b + nn1 * 32,
                 * p2 = t1b + nn2 * 32, *p3 = t1b + nn3 * 32;
    const __half2* q0 = t2b + nn0 * 32, *q1 = t2b + nn1 * 32,
                 * q2 = t2b + nn2 * 32, *q3 = t2b + nn3 * 32;
    float4 acc0 = {0, 0, 0, 0}, acc1 = {0, 0, 0, 0},
           acc2 = {0, 0, 0, 0}, acc3 = {0, 0, 0, 0};
#pragma unroll 4
    for (int i = 0; i < 32; i++) {
        int ka = 2 * i, kb = 2 * i + 1;
        float4 w0a = *(const float4*)&sW[(0 * 64 + ka) * 64 + c0];
        float4 w0b = *(const float4*)&sW[(0 * 64 + kb) * 64 + c0];
        float4 w1a = *(const float4*)&sW[(1 * 64 + ka) * 64 + c0];
        float4 w1b = *(const float4*)&sW[(1 * 64 + kb) * 64 + c0];
        float4 w2a = *(const float4*)&sW[(2 * 64 + ka) * 64 + c0];
        float4 w2b = *(const float4*)&sW[(2 * 64 + kb) * 64 + c0];
#define DO_NODE(acc, hp, pp, qp)                                              \
        {                                                                     \
            float2 hv  = __half22float2(__ldg(&hp[i]));                       \
            float2 t1v = __half22float2(__ldg(&pp[i]));                       \
            float2 t2v = __half22float2(__ldg(&qp[i]));                       \
            acc.x += hv.x * w0a.x + hv.y * w0b.x + t1v.x * w1a.x              \
                   + t1v.y * w1b.x + t2v.x * w2a.x + t2v.y * w2b.x;           \
            acc.y += hv.x * w0a.y + hv.y * w0b.y + t1v.x * w1a.y              \
                   + t1v.y * w1b.y + t2v.x * w2a.y + t2v.y * w2b.y;           \
            acc.z += hv.x * w0a.z + hv.y * w0b.z + t1v.x * w1a.z              \
                   + t1v.y * w1b.z + t2v.x * w2a.z + t2v.y * w2b.z;           \
            acc.w += hv.x * w0a.w + hv.y * w0b.w + t1v.x * w1a.w              \
                   + t1v.y * w1b.w + t2v.x * w2a.w + t2v.y * w2b.w;           \
        }
        DO_NODE(acc0, h0, p0, q0)
        DO_NODE(acc1, h1, p1, q1)
        DO_NODE(acc2, h2, p2, q2)
        DO_NODE(acc3, h3, p3, q3)
#undef DO_NODE
    }
    float a = __ldg(&a_ptr[0]);
    __half2* outb = (__half2*)hbuf_sel(out_sel);
#define EMIT(acc, node)                                                       \
    if ((node) < NN) {                                                        \
        unsigned base = (unsigned)((node) * FD + c0);                         \
        float r0 = act_apply(acc.x, base + 0u, k0, k1, a);                    \
        float r1 = act_apply(acc.y, base + 1u, k0, k1, a);                    \
        float r2 = act_apply(acc.z, base + 2u, k0, k1, a);                    \
        float r3 = act_apply(acc.w, base + 3u, k0, k1, a);                    \
        __half2* op = outb + (node) * 32 + c0 / 2;                            \
        op[0] = __floats2half2_rn(r0, r1);                                    \
        op[1] = __floats2half2_rn(r2, r3);                                    \
    }
    EMIT(acc0, n0)
    EMIT(acc1, n0 + 1)
    EMIT(acc2, n0 + 2)
    EMIT(acc3, n0 + 3)
#undef EMIT
}

// ---------------- 3-way projection: s_k[n] = G2h[n,:] @ W2[k,:,0] ----------
__global__ void proj3_kernel(const float* __restrict__ W) {  // (3,64,1)
    int warp = (blockIdx.x * blockDim.x + threadIdx.x) >> 5;
    int lane = threadIdx.x & 31;
    if (warp >= NN) return;
    int i0 = lane * 2;
    float2 g = __half22float2(((const __half2*)g_G2h)[warp * 32 + lane]);
    float s0 = g.x * __ldg(&W[i0])       + g.y * __ldg(&W[i0 + 1]);
    float s1 = g.x * __ldg(&W[64 + i0])  + g.y * __ldg(&W[64 + i0 + 1]);
    float s2 = g.x * __ldg(&W[128 + i0]) + g.y * __ldg(&W[128 + i0 + 1]);
#pragma unroll
    for (int off = 16; off; off >>= 1) {
        s0 += __shfl_down_sync(0xFFFFFFFFu, s0, off);
        s1 += __shfl_down_sync(0xFFFFFFFFu, s1, off);
        s2 += __shfl_down_sync(0xFFFFFFFFu, s2, off);
    }
    if (lane == 0) {
        g_s0[warp] = s0;
        g_s1[warp] = s1;
        g_s2[warp] = s2;
    }
}

// ---------------- 1-wide SpMM: out[n] = add[n] + sum w_e * vin[src_e] -------
__global__ void spmm1_kernel(int in_sel, int add_sel, int out_sel,
                             float* __restrict__ out_ext) {
    int n = blockIdx.x * blockDim.x + threadIdx.x;
    if (n >= NN) return;
    const float* __restrict__ vin = vec_sel(in_sel);
    float* __restrict__ vout = (out_sel < 0) ? out_ext : vec_sel(out_sel);
    int s = g_rowptr[n];
    int e = g_rowptr[n + 1];
    float acc = 0.0f;
    int j = s;
    for (; j + 4 <= e; j += 4) {
        int2 e0 = g_edge[j];
        int2 e1 = g_edge[j + 1];
        int2 e2 = g_edge[j + 2];
        int2 e3 = g_edge[j + 3];
        float v0 = __ldg(&vin[e0.x]);
        float v1 = __ldg(&vin[e1.x]);
        float v2 = __ldg(&vin[e2.x]);
        float v3 = __ldg(&vin[e3.x]);
        acc += __int_as_float(e0.y) * v0 + __int_as_float(e1.y) * v1
             + __int_as_float(e2.y) * v2 + __int_as_float(e3.y) * v3;
    }
    for (; j < e; j++) {
        int2 ed = g_edge[j];
        acc += __int_as_float(ed.y) * __ldg(&vin[ed.x]);
    }
    vout[n] = vec_sel(add_sel)[n] + acc;
}

// ============================================================================
extern "C" void kernel_launch(void* const* d_in, const int* in_sizes, int n_in,
                              void* d_out, int out_size) {
    const float* x  = (const float*)d_in[0];
    const int*   ei = (const int*)d_in[1];     // int32: JAX x64-disabled
    const float* ea = (const float*)d_in[2];
    const float* W0 = (const float*)d_in[3];
    const float* W1 = (const float*)d_in[4];
    const float* W2 = (const float*)d_in[5];
    const float* a0 = (const float*)d_in[6];
    const float* a1 = (const float*)d_in[7];
    float* out = (float*)d_out;

    // host-side Threefry: dropout subkeys from jax.random.key(42) = (0, 42)
    unsigned dk0_0, dk0_1, dk1_0, dk1_1;
    tf2x32(0u, 42u, 0u, 0u, dk0_0, dk0_1);
    tf2x32(0u, 42u, 0u, 1u, dk1_0, dk1_1);

    const int TB = 256;
    const int gN  = (NN + TB - 1) / TB;
    const int gE  = (EE + TB - 1) / TB;
    const int gS  = (NN * 8 + TB - 1) / TB;    // 8 lanes per node (spmmh)
    const int gW  = (NN * 32 + TB - 1) / TB;   // warp per node (proj3)
    const int gC  = (NN * (FD / 2) + TB - 1) / TB;
    const int gD  = (NN + DNB - 1) / DNB;      // 64 nodes per block

    // ---- graph preprocessing (CSR by target) ----
    zero_kernel<<<gN, TB>>>();
    deg_kernel<<<gE, TB>>>(ei, ea);
    dinv_kernel<<<gN, TB>>>();
    scan1_kernel<<<NSB, SB>>>();
    scan2_kernel<<<1, 64>>>();
    scan3_kernel<<<NSB, SB>>>();
    sort_kernel<<<gE, TB>>>(ei, ea);
    cvt_kernel<<<gC, TB>>>(x);

    // ---- layer 0: Xh -> G1h ----
    spmmh_kernel<<<gS, TB>>>(HB_X, HB_T1);
    spmmh_kernel<<<gS, TB>>>(HB_T1, HB_T2);
    dense64_kernel<<<gD, TB>>>(HB_X, W0, HB_G1, a0, dk0_0, dk0_1);

    // ---- layer 1: G1h -> G2h ----
    spmmh_kernel<<<gS, TB>>>(HB_G1, HB_T1);
    spmmh_kernel<<<gS, TB>>>(HB_T1, HB_T2);
    dense64_kernel<<<gD, TB>>>(HB_G1, W1, HB_G2, a1, dk1_0, dk1_1);

    // ---- layer 2 (projection-first): out = s0 + A(s1 + A s2) ----
    proj3_kernel<<<gW, TB>>>(W2);
    spmm1_kernel<<<gN, TB>>>(VEC_S2, VEC_S1, VEC_U, nullptr);  // u = s1 + A s2
    spmm1_kernel<<<gN, TB>>>(VEC_U, VEC_S0, -1, out);          // out = s0 + A u
}